// round 10
// baseline (speedup 1.0000x reference)
#include <cuda_runtime.h>
#include <cuda_bf16.h>
#include <cuda_fp16.h>
#include <math.h>
#include <cstdint>

// Problem constants
#define B_   4
#define CIN  256
#define N_   4096        // 64*64 tokens
#define H_   4
#define D_   32
#define HID  128
#define O3   384
#define BH   16

// ---------------------------------------------------------------------------
// Scratch (device globals)
__device__ __half  g_q   [(size_t)BH * N_ * D_];   // [bh][i][d] fp16, pre-scaled 32^-.5*log2e
__device__ __half  g_k   [(size_t)BH * N_ * D_];   // [bh][j][d] fp16
__device__ __half  g_v   [(size_t)BH * D_ * N_];   // [bh][d][j] fp16
__device__ float   g_att [(size_t)B_ * HID * N_];  // [b*128+c][i]

// ---------------------------------------------------------------------------
__device__ __forceinline__ uint32_t packh2(float a, float b) {
    __half2 h = __floats2half2_rn(a, b);
    return *reinterpret_cast<uint32_t*>(&h);
}
__device__ __forceinline__ void split2h(float a, float b, uint32_t& hi, uint32_t& lo) {
    __half2 h = __floats2half2_rn(a, b);
    hi = *reinterpret_cast<uint32_t*>(&h);
    lo = packh2(a - __half2float(__low2half(h)), b - __half2float(__high2half(h)));
}
__device__ __forceinline__ float ex2f(float x) {
    float y;
    asm("ex2.approx.ftz.f32 %0, %1;" : "=f"(y) : "f"(x));
    return y;
}
__device__ __forceinline__ void mma16816h(float* c, const uint32_t* a, uint32_t b0, uint32_t b1) {
    asm volatile("mma.sync.aligned.m16n8k16.row.col.f32.f16.f16.f32 "
                 "{%0,%1,%2,%3}, {%4,%5,%6,%7}, {%8,%9}, {%0,%1,%2,%3};"
                 : "+f"(c[0]), "+f"(c[1]), "+f"(c[2]), "+f"(c[3])
                 : "r"(a[0]), "r"(a[1]), "r"(a[2]), "r"(a[3]), "r"(b0), "r"(b1));
}
__device__ __forceinline__ void ldm_x4(uint32_t* r, uint32_t addr) {
    asm volatile("ldmatrix.sync.aligned.m8n8.x4.shared.b16 {%0,%1,%2,%3}, [%4];"
                 : "=r"(r[0]), "=r"(r[1]), "=r"(r[2]), "=r"(r[3]) : "r"(addr));
}
__device__ __forceinline__ void ldm_x4_t(uint32_t* r, uint32_t addr) {
    asm volatile("ldmatrix.sync.aligned.m8n8.x4.trans.shared.b16 {%0,%1,%2,%3}, [%4];"
                 : "=r"(r[0]), "=r"(r[1]), "=r"(r[2]), "=r"(r[3]) : "r"(addr));
}
__device__ __forceinline__ uint32_t smem_u32(const void* p) {
    uint32_t a;
    asm("{ .reg .u64 t; cvta.to.shared.u64 t, %1; cvt.u32.u64 %0, t; }" : "=r"(a) : "l"(p));
    return a;
}
#define CPA16(dst, src) \
    asm volatile("cp.async.cg.shared.global [%0], [%1], 16;" :: "r"(dst), "l"(src))

// ---------------------------------------------------------------------------
// Projection GEMM core: fp16, A split 2-term, C tile 64(m) x 128(n), K-chunk 32.
// 8 warps: wRow = wid&3 (m16 each), wCol = wid>>2 (n64 each).
// smem (uint32 words): A-hi 64x20w, A-lo @1280, B @2560 (32x68w); stage 64x129 f.
#define AW     20
#define BW     68
#define OFF_AL 1280
#define OFF_B  2560
#define SMEMW  8256
#define STG    129

struct CR { float4 a[2]; float4 b[4]; };

__device__ __forceinline__ void ldg_chunk(CR& r, const float* Aptr, const float* Bptr,
                                          int k0, int kdim, int nBase, int tid)
{
#pragma unroll
    for (int i = 0; i < 2; i++) {
        int m = (tid >> 3) + i * 32;
        int j8 = tid & 7;
        r.a[i] = *(const float4*)(Aptr + (size_t)m * kdim + k0 + j8 * 4);
    }
#pragma unroll
    for (int i = 0; i < 4; i++) {
        int kr = (tid >> 5) + i * 8;
        int j  = tid & 31;
        r.b[i] = *(const float4*)(Bptr + (size_t)(k0 + kr) * N_ + nBase + j * 4);
    }
}

__device__ __forceinline__ void sts_chunk(uint32_t* sm, const CR& r, int tid)
{
#pragma unroll
    for (int i = 0; i < 2; i++) {
        int m = (tid >> 3) + i * 32;
        int j8 = tid & 7;
        uint32_t h0, l0, h1, l1;
        split2h(r.a[i].x, r.a[i].y, h0, l0);
        split2h(r.a[i].z, r.a[i].w, h1, l1);
        int idx = m * AW + j8 * 2;
        sm[idx] = h0; sm[idx + 1] = h1;
        sm[OFF_AL + idx] = l0; sm[OFF_AL + idx + 1] = l1;
    }
#pragma unroll
    for (int i = 0; i < 4; i++) {
        int kr = (tid >> 5) + i * 8;
        int j  = tid & 31;
        int idx = kr * BW + j * 2;
        sm[OFF_B + idx]     = packh2(r.b[i].x, r.b[i].y);
        sm[OFF_B + idx + 1] = packh2(r.b[i].z, r.b[i].w);
    }
}

__device__ __forceinline__ void mma_chunk(float (*C)[4], uint32_t sb, int wid, int lane)
{
    const int wRow = wid & 3, wCol = wid >> 2;
    const uint32_t aRow = (uint32_t)(wRow * 16 + (lane & 15));
    const uint32_t aCol = (uint32_t)((lane >> 4) << 4);
    const uint32_t bRow = (uint32_t)(((lane >> 3) & 1) * 8 + (lane & 7));
    const uint32_t bCol = (uint32_t)((lane >> 4) << 4);
#pragma unroll
    for (int ks = 0; ks < 2; ks++) {
        uint32_t ah[4], al[4];
        ldm_x4(ah, sb + aRow * 80 + ks * 32 + aCol);
        ldm_x4(al, sb + OFF_AL * 4 + aRow * 80 + ks * 32 + aCol);
#pragma unroll
        for (int nbp = 0; nbp < 4; nbp++) {
            uint32_t bb[4];
            uint32_t ro = (ks * 16 + bRow) * 272 + (wCol * 4 + nbp) * 32 + bCol;
            ldm_x4_t(bb, sb + OFF_B * 4 + ro);
            int nb0 = 2 * nbp, nb1 = nb0 + 1;
            mma16816h(C[nb0], ah, bb[0], bb[1]);
            mma16816h(C[nb0], al, bb[0], bb[1]);
            mma16816h(C[nb1], ah, bb[2], bb[3]);
            mma16816h(C[nb1], al, bb[2], bb[3]);
        }
    }
}

__device__ __forceinline__ void stage_all(float* stg, float (*C)[4], int wid, int lane)
{
    const int wRow = wid & 3, wCol = wid >> 2;
    int m0 = wRow * 16 + (lane >> 2);
    int nb0 = (lane & 3) * 2;
#pragma unroll
    for (int nb = 0; nb < 8; nb++) {
        int n = wCol * 64 + nb * 8 + nb0;
        stg[m0 * STG + n]           = C[nb][0];
        stg[m0 * STG + n + 1]       = C[nb][1];
        stg[(m0 + 8) * STG + n]     = C[nb][2];
        stg[(m0 + 8) * STG + n + 1] = C[nb][3];
    }
}

// ---------------------------------------------------------------------------
// Kernel A: qkv projection. grid (32 n, 6 o64, 4 b), 256 thr.
// ---------------------------------------------------------------------------
__global__ void __launch_bounds__(256, 2) qkv_mma_kernel(const float* __restrict__ x,
                                                         const float* __restrict__ w)
{
    __shared__ __align__(16) uint32_t sm[SMEMW];
    float* stg = (float*)sm;

    const int tid  = threadIdx.x;
    const int wid  = tid >> 5;
    const int lane = tid & 31;
    const int nBase = blockIdx.x * 128;
    const int by    = blockIdx.y;          // o-block of 64: sec = by>>1, half = by&1
    const int b     = blockIdx.z;
    const int sec   = by >> 1;
    const int half  = by & 1;
    const uint32_t sb = smem_u32(sm);

    const float* Aptr = w + (size_t)(by * 64) * CIN;
    const float* Bptr = x + (size_t)b * CIN * N_;

    float C[8][4];
#pragma unroll
    for (int i = 0; i < 8; i++)
#pragma unroll
        for (int j = 0; j < 4; j++) C[i][j] = 0.f;

    CR r;
    ldg_chunk(r, Aptr, Bptr, 0, CIN, nBase, tid);
#pragma unroll 1
    for (int k0 = 0; k0 < CIN; k0 += 32) {
        __syncthreads();
        sts_chunk(sm, r, tid);
        __syncthreads();
        if (k0 + 32 < CIN) ldg_chunk(r, Aptr, Bptr, k0 + 32, CIN, nBase, tid);
        mma_chunk(C, sb, wid, lane);
    }

    // q scale folds in log2(e) so attention can use ex2 directly
    const float scale = 0.17677669529663687f * 1.4426950408889634f;

    __syncthreads();
    stage_all(stg, C, wid, lane);
    __syncthreads();

    if (sec <= 1) {
        // q (scaled) / k : fp16 [bh][i|j][d]
        int seg = tid >> 7, n = tid & 127;
        int h = half * 2 + seg;
        float s0 = (sec == 0) ? scale : 1.f;
        uint32_t wv[16];
#pragma unroll
        for (int l = 0; l < 16; l++)
            wv[l] = packh2(stg[(seg * 32 + 2 * l) * STG + n] * s0,
                           stg[(seg * 32 + 2 * l + 1) * STG + n] * s0);
        __half* dstp = (sec == 0) ? g_q : g_k;
        uint4* dk = (uint4*)(dstp + ((size_t)(b * H_ + h) * N_ + nBase + n) * D_);
#pragma unroll
        for (int i = 0; i < 4; i++) dk[i] = ((uint4*)wv)[i];
    } else {
        // V: fp16 [bh][d][j]
        int mrow = tid & 63, n0 = (tid >> 6) * 32;
        int o = half * 64 + mrow;
        int h = o >> 5, d = o & 31;
        uint32_t hw[16];
#pragma unroll
        for (int l = 0; l < 16; l++)
            hw[l] = packh2(stg[mrow * STG + n0 + 2 * l],
                           stg[mrow * STG + n0 + 2 * l + 1]);
        uint4* dv = (uint4*)(g_v + ((size_t)(b * H_ + h) * D_ + d) * N_ + nBase + n0);
#pragma unroll
        for (int i = 0; i < 4; i++) dv[i] = ((uint4*)hw)[i];
    }
}

// ---------------------------------------------------------------------------
// Kernel C: out projection. grid (32 n, 4 o64, 4 b), 256 thr.
// ---------------------------------------------------------------------------
__global__ void __launch_bounds__(256, 2) out_mma_kernel(const float* __restrict__ w,
                                                         const float* __restrict__ bias,
                                                         float* __restrict__ out)
{
    __shared__ __align__(16) uint32_t sm[SMEMW];
    float* stg = (float*)sm;

    const int tid  = threadIdx.x;
    const int wid  = tid >> 5;
    const int lane = tid & 31;
    const int nBase = blockIdx.x * 128;
    const int oBase = blockIdx.y * 64;
    const int b     = blockIdx.z;
    const uint32_t sb = smem_u32(sm);

    const float* Aptr = w + (size_t)oBase * HID;
    const float* Bptr = g_att + (size_t)b * HID * N_;

    float C[8][4];
#pragma unroll
    for (int i = 0; i < 8; i++)
#pragma unroll
        for (int j = 0; j < 4; j++) C[i][j] = 0.f;

    CR r;
    ldg_chunk(r, Aptr, Bptr, 0, HID, nBase, tid);
#pragma unroll 1
    for (int k0 = 0; k0 < HID; k0 += 32) {
        __syncthreads();
        sts_chunk(sm, r, tid);
        __syncthreads();
        if (k0 + 32 < HID) ldg_chunk(r, Aptr, Bptr, k0 + 32, HID, nBase, tid);
        mma_chunk(C, sb, wid, lane);
    }

    __syncthreads();
    stage_all(stg, C, wid, lane);
    __syncthreads();

    int rr = tid & 63, n0 = (tid >> 6) * 32;
    int o = oBase + rr;
    float bv = bias[o];
    float v[32];
#pragma unroll
    for (int i = 0; i < 32; i++) v[i] = stg[rr * STG + n0 + i] + bv;
    float4* dst = (float4*)(out + ((size_t)(b * CIN + o)) * N_ + nBase + n0);
#pragma unroll
    for (int i = 0; i < 8; i++) dst[i] = ((float4*)v)[i];
}

// ---------------------------------------------------------------------------
// Kernel B: flash attention, fp16 mma, single-term S and PV. 3-stage cp.async,
// ONE __syncthreads per tile. grid (32 qtiles, 16 bh), 256 thr. Key tile = 64.
// smem/stage: K 64x80B + V 32x144B = 9728 B, 3 stages = 29184 B.
// ---------------------------------------------------------------------------
#define KOFF    0
#define VOFF    5120
#define STAGE_B 9728
#define NTILES  (N_ / 64)

__global__ void __launch_bounds__(256, 2) attn_mma_kernel()
{
    __shared__ __align__(16) char smb[3 * STAGE_B];
    const uint32_t sb = smem_u32(smb);

    const int tid  = threadIdx.x;
    const int wid  = tid >> 5;
    const int lane = tid & 31;
    const int lq   = lane >> 2;
    const int lr   = lane & 3;

    const int bh = blockIdx.y;
    const int qt = blockIdx.x;

    const char* KG = (const char*)(g_k + (size_t)bh * N_ * D_);
    const char* VG = (const char*)(g_v + (size_t)bh * D_ * N_);
    const int krow = tid >> 2, kseg = tid & 3;
    const int vrow = tid >> 3, vseg = tid & 7;
    const uint32_t kDst = (uint32_t)(krow * 80 + kseg * 16);
    const uint32_t vDst = (uint32_t)(vrow * 144 + vseg * 16);
    const int kSrc = krow * 64 + kseg * 16;     // + jt*64 bytes
    const int vSrc = vrow * 8192 + vseg * 16;   // + jt*2 bytes

    const int rbase = ((lane >> 4) << 3) + (lane & 7);
    const int coff  = (lane & 8) << 1;

    // ---- Q A-frags: single fp16, loaded directly from gmem ----
    uint32_t qf[2][4];
    {
        const __half* Qg = g_q + ((size_t)bh * N_ + qt * 128 + wid * 16) * D_;
#pragma unroll
        for (int ks = 0; ks < 2; ks++) {
            int c0 = ks * 16 + lr * 2;
            qf[ks][0] = *(const uint32_t*)(Qg + (size_t)lq * D_ + c0);
            qf[ks][1] = *(const uint32_t*)(Qg + (size_t)(lq + 8) * D_ + c0);
            qf[ks][2] = *(const uint32_t*)(Qg + (size_t)lq * D_ + c0 + 8);
            qf[ks][3] = *(const uint32_t*)(Qg + (size_t)(lq + 8) * D_ + c0 + 8);
        }
    }

    float O[4][4];
#pragma unroll
    for (int a = 0; a < 4; a++)
#pragma unroll
        for (int c = 0; c < 4; c++) O[a][c] = 0.f;
    float lrow0 = 0.f, lrow1 = 0.f;

    // prologue: tiles 0,1 -> stages 0,1
#pragma unroll
    for (int p = 0; p < 2; p++) {
        uint32_t s = sb + p * STAGE_B;
        CPA16(s + KOFF + kDst, KG + p * 64 * 64 + kSrc);
        CPA16(s + VOFF + vDst, VG + p * 64 * 2 + vSrc);
        asm volatile("cp.async.commit_group;");
    }

    int stage = 0;
#pragma unroll 1
    for (int t = 0; t < NTILES; t++) {
        // tile t is the oldest outstanding group; leave at most t+1 in flight
        if (t + 1 < NTILES) asm volatile("cp.async.wait_group 1;" ::: "memory");
        else                asm volatile("cp.async.wait_group 0;" ::: "memory");
        __syncthreads();   // data of tile t visible; all warps done with tile t-1

        if (t + 2 < NTILES) {
            int ps = stage + 2; if (ps >= 3) ps -= 3;   // stage of t-1, now free
            const int jt = (t + 2) * 64;
            uint32_t s2 = sb + ps * STAGE_B;
            CPA16(s2 + KOFF + kDst, KG + jt * 64 + kSrc);
            CPA16(s2 + VOFF + vDst, VG + jt * 2 + vSrc);
            asm volatile("cp.async.commit_group;");
        }

        const uint32_t s = sb + stage * STAGE_B;

        // ---- S = Q K^T + softmax (ex2) ----
        uint32_t Pf[4][4];
#pragma unroll
        for (int nbp = 0; nbp < 4; nbp++) {
            float S0[4] = {0.f, 0.f, 0.f, 0.f};
            float S1[4] = {0.f, 0.f, 0.f, 0.f};
#pragma unroll
            for (int ks = 0; ks < 2; ks++) {
                uint32_t kk[4];
                ldm_x4(kk, s + KOFF + (uint32_t)((nbp * 16 + rbase) * 80 + ks * 32 + coff));
                mma16816h(S0, qf[ks], kk[0], kk[1]);
                mma16816h(S1, qf[ks], kk[2], kk[3]);
            }
            float p0 = ex2f(S0[0]);
            float p1 = ex2f(S0[1]);
            float p2 = ex2f(S0[2]);
            float p3 = ex2f(S0[3]);
            float r0 = ex2f(S1[0]);
            float r1 = ex2f(S1[1]);
            float r2 = ex2f(S1[2]);
            float r3 = ex2f(S1[3]);
            lrow0 += p0 + p1 + r0 + r1;
            lrow1 += p2 + p3 + r2 + r3;
            Pf[nbp][0] = packh2(p0, p1);
            Pf[nbp][1] = packh2(p2, p3);
            Pf[nbp][2] = packh2(r0, r1);
            Pf[nbp][3] = packh2(r2, r3);
        }

        // ---- O += P V ----
#pragma unroll
        for (int ts = 0; ts < 4; ts++) {
#pragma unroll
            for (int dbp = 0; dbp < 2; dbp++) {
                uint32_t vv[4];
                ldm_x4(vv, s + VOFF + (uint32_t)((dbp * 16 + rbase) * 144 + ts * 32 + coff));
                mma16816h(O[2 * dbp],     Pf[ts], vv[0], vv[1]);
                mma16816h(O[2 * dbp + 1], Pf[ts], vv[2], vv[3]);
            }
        }

        stage++; if (stage == 3) stage = 0;
    }

    // ---- reduce row sums across the 4 lanes sharing a row ----
    lrow0 += __shfl_xor_sync(0xFFFFFFFFu, lrow0, 1);
    lrow0 += __shfl_xor_sync(0xFFFFFFFFu, lrow0, 2);
    lrow1 += __shfl_xor_sync(0xFFFFFFFFu, lrow1, 1);
    lrow1 += __shfl_xor_sync(0xFFFFFFFFu, lrow1, 2);
    const float inv0 = 1.f / lrow0;
    const float inv1 = 1.f / lrow1;

    // ---- write O to g_att [bh*32+d][i] ----
    const int i0 = qt * 128 + wid * 16 + lq;
    float* base = g_att + (size_t)bh * D_ * N_;
#pragma unroll
    for (int db = 0; db < 4; db++) {
        int d = db * 8 + lr * 2;
        base[(size_t)d * N_ + i0]           = O[db][0] * inv0;
        base[(size_t)(d + 1) * N_ + i0]     = O[db][1] * inv0;
        base[(size_t)d * N_ + i0 + 8]       = O[db][2] * inv1;
        base[(size_t)(d + 1) * N_ + i0 + 8] = O[db][3] * inv1;
    }
}

// ---------------------------------------------------------------------------
extern "C" void kernel_launch(void* const* d_in, const int* in_sizes, int n_in,
                              void* d_out, int out_size)
{
    (void)in_sizes; (void)n_in; (void)out_size;
    const float* x     = (const float*)d_in[0];
    const float* w_qkv = (const float*)d_in[1];
    const float* w_out = (const float*)d_in[2];
    const float* b_out = (const float*)d_in[3];
    float* out = (float*)d_out;

    dim3 gA(N_ / 128, 6, B_);
    qkv_mma_kernel<<<gA, 256>>>(x, w_qkv);

    dim3 gB(N_ / 128, BH);
    attn_mma_kernel<<<gB, 256>>>();

    dim3 gC(N_ / 128, 4, B_);
    out_mma_kernel<<<gC, 256>>>(w_out, b_out, out);
}

// round 11
// speedup vs baseline: 1.5905x; 1.5905x over previous
#include <cuda_runtime.h>
#include <cuda_bf16.h>
#include <cuda_fp16.h>
#include <math.h>
#include <cstdint>

// Problem constants
#define B_   4
#define CIN  256
#define N_   4096        // 64*64 tokens
#define H_   4
#define D_   32
#define HID  128
#define O3   384
#define BH   16

// ---------------------------------------------------------------------------
// Scratch (device globals)
__device__ __half  g_q   [(size_t)BH * N_ * D_];   // [bh][i][d] fp16, pre-scaled 32^-.5*log2e
__device__ __half  g_k   [(size_t)BH * N_ * D_];   // [bh][j][d] fp16
__device__ __half  g_v   [(size_t)BH * D_ * N_];   // [bh][d][j] fp16
__device__ float   g_att [(size_t)B_ * HID * N_];  // [b*128+c][i]

// ---------------------------------------------------------------------------
__device__ __forceinline__ uint32_t packh2(float a, float b) {
    __half2 h = __floats2half2_rn(a, b);
    return *reinterpret_cast<uint32_t*>(&h);
}
__device__ __forceinline__ void split2h(float a, float b, uint32_t& hi, uint32_t& lo) {
    __half2 h = __floats2half2_rn(a, b);
    hi = *reinterpret_cast<uint32_t*>(&h);
    lo = packh2(a - __half2float(__low2half(h)), b - __half2float(__high2half(h)));
}
__device__ __forceinline__ float ex2f(float x) {
    float y;
    asm("ex2.approx.ftz.f32 %0, %1;" : "=f"(y) : "f"(x));
    return y;
}
__device__ __forceinline__ void mma16816h(float* c, const uint32_t* a, uint32_t b0, uint32_t b1) {
    asm volatile("mma.sync.aligned.m16n8k16.row.col.f32.f16.f16.f32 "
                 "{%0,%1,%2,%3}, {%4,%5,%6,%7}, {%8,%9}, {%0,%1,%2,%3};"
                 : "+f"(c[0]), "+f"(c[1]), "+f"(c[2]), "+f"(c[3])
                 : "r"(a[0]), "r"(a[1]), "r"(a[2]), "r"(a[3]), "r"(b0), "r"(b1));
}
__device__ __forceinline__ void ldm_x4(uint32_t* r, uint32_t addr) {
    asm volatile("ldmatrix.sync.aligned.m8n8.x4.shared.b16 {%0,%1,%2,%3}, [%4];"
                 : "=r"(r[0]), "=r"(r[1]), "=r"(r[2]), "=r"(r[3]) : "r"(addr));
}
__device__ __forceinline__ void ldm_x4_t(uint32_t* r, uint32_t addr) {
    asm volatile("ldmatrix.sync.aligned.m8n8.x4.trans.shared.b16 {%0,%1,%2,%3}, [%4];"
                 : "=r"(r[0]), "=r"(r[1]), "=r"(r[2]), "=r"(r[3]) : "r"(addr));
}
__device__ __forceinline__ uint32_t smem_u32(const void* p) {
    uint32_t a;
    asm("{ .reg .u64 t; cvta.to.shared.u64 t, %1; cvt.u32.u64 %0, t; }" : "=r"(a) : "l"(p));
    return a;
}
#define CPA16(dst, src) \
    asm volatile("cp.async.cg.shared.global [%0], [%1], 16;" :: "r"(dst), "l"(src))

// ---------------------------------------------------------------------------
// Projection GEMM core: fp16, A split 2-term (AhB + AlB), C tile 128(m) x 128(n),
// K-chunk 32. smem (uint32 words): A-hi 128x20w, A-lo @2560, B @5120 (32x68w).
// Epilogue stage (float) reuses smem: 64x129.
#define AW     20
#define BW     68
#define OFF_AL 2560
#define OFF_B  5120
#define SMEMW  8256
#define STG    129

struct CR { float4 a[4]; float4 b[4]; };

__device__ __forceinline__ void ldg_chunk(CR& r, const float* Aptr, const float* Bptr,
                                          int k0, int kdim, int nBase, int tid)
{
#pragma unroll
    for (int i = 0; i < 4; i++) {
        int m = (tid >> 3) + i * 32;
        int j8 = tid & 7;
        r.a[i] = *(const float4*)(Aptr + (size_t)m * kdim + k0 + j8 * 4);
    }
#pragma unroll
    for (int i = 0; i < 4; i++) {
        int kr = (tid >> 5) + i * 8;
        int j  = tid & 31;
        r.b[i] = *(const float4*)(Bptr + (size_t)(k0 + kr) * N_ + nBase + j * 4);
    }
}

__device__ __forceinline__ void sts_chunk(uint32_t* sm, const CR& r, int tid)
{
#pragma unroll
    for (int i = 0; i < 4; i++) {
        int m = (tid >> 3) + i * 32;
        int j8 = tid & 7;
        uint32_t h0, l0, h1, l1;
        split2h(r.a[i].x, r.a[i].y, h0, l0);
        split2h(r.a[i].z, r.a[i].w, h1, l1);
        int idx = m * AW + j8 * 2;
        sm[idx] = h0; sm[idx + 1] = h1;
        sm[OFF_AL + idx] = l0; sm[OFF_AL + idx + 1] = l1;
    }
#pragma unroll
    for (int i = 0; i < 4; i++) {
        int kr = (tid >> 5) + i * 8;
        int j  = tid & 31;
        int idx = kr * BW + j * 2;
        sm[OFF_B + idx]     = packh2(r.b[i].x, r.b[i].y);
        sm[OFF_B + idx + 1] = packh2(r.b[i].z, r.b[i].w);
    }
}

__device__ __forceinline__ void mma_chunk(float (*C)[4], uint32_t sb, int wid, int lane)
{
    const uint32_t aRow = (uint32_t)(wid * 16 + (lane & 15));
    const uint32_t aCol = (uint32_t)((lane >> 4) << 4);
    const uint32_t bRow = (uint32_t)(((lane >> 3) & 1) * 8 + (lane & 7));
    const uint32_t bCol = (uint32_t)((lane >> 4) << 4);
#pragma unroll
    for (int ks = 0; ks < 2; ks++) {
        uint32_t ah[4], al[4];
        ldm_x4(ah, sb + aRow * 80 + ks * 32 + aCol);
        ldm_x4(al, sb + OFF_AL * 4 + aRow * 80 + ks * 32 + aCol);
#pragma unroll
        for (int nbp = 0; nbp < 8; nbp++) {
            uint32_t bb[4];
            uint32_t ro = (ks * 16 + bRow) * 272 + nbp * 32 + bCol;
            ldm_x4_t(bb, sb + OFF_B * 4 + ro);
            int nb0 = 2 * nbp, nb1 = nb0 + 1;
            mma16816h(C[nb0], ah, bb[0], bb[1]);
            mma16816h(C[nb0], al, bb[0], bb[1]);
            mma16816h(C[nb1], ah, bb[2], bb[3]);
            mma16816h(C[nb1], al, bb[2], bb[3]);
        }
    }
}

__device__ __forceinline__ void stage_half(float* stg, float (*C)[4], int wid,
                                           int lane, int half)
{
    if ((wid >> 2) == half) {
        int m0 = (wid & 3) * 16 + (lane >> 2);
        int n0 = (lane & 3) * 2;
#pragma unroll
        for (int nb = 0; nb < 16; nb++) {
            int n = nb * 8 + n0;
            stg[m0 * STG + n]           = C[nb][0];
            stg[m0 * STG + n + 1]       = C[nb][1];
            stg[(m0 + 8) * STG + n]     = C[nb][2];
            stg[(m0 + 8) * STG + n + 1] = C[nb][3];
        }
    }
}

// ---------------------------------------------------------------------------
// Kernel A: qkv projection. grid (32 n, 3 sec, 4 b), 256 thr.
// ---------------------------------------------------------------------------
__global__ void __launch_bounds__(256) qkv_mma_kernel(const float* __restrict__ x,
                                                      const float* __restrict__ w)
{
    __shared__ __align__(16) uint32_t sm[SMEMW];
    float* stg = (float*)sm;

    const int tid  = threadIdx.x;
    const int wid  = tid >> 5;
    const int lane = tid & 31;
    const int nBase = blockIdx.x * 128;
    const int sec   = blockIdx.y;
    const int b     = blockIdx.z;
    const uint32_t sb = smem_u32(sm);

    const float* Aptr = w + (size_t)(sec * 128) * CIN;
    const float* Bptr = x + (size_t)b * CIN * N_;

    float C[16][4];
#pragma unroll
    for (int i = 0; i < 16; i++)
#pragma unroll
        for (int j = 0; j < 4; j++) C[i][j] = 0.f;

    CR r;
    ldg_chunk(r, Aptr, Bptr, 0, CIN, nBase, tid);
#pragma unroll 1
    for (int k0 = 0; k0 < CIN; k0 += 32) {
        __syncthreads();
        sts_chunk(sm, r, tid);
        __syncthreads();
        if (k0 + 32 < CIN) ldg_chunk(r, Aptr, Bptr, k0 + 32, CIN, nBase, tid);
        mma_chunk(C, sb, wid, lane);
    }

    // q scale folds in log2(e) so attention can use ex2 directly
    const float scale = 0.17677669529663687f * 1.4426950408889634f;

#pragma unroll 1
    for (int half = 0; half < 2; half++) {
        __syncthreads();
        stage_half(stg, C, wid, lane, half);
        __syncthreads();

        if (sec <= 1) {
            // q (scaled) / k : fp16 [bh][i|j][d]
            int seg = tid >> 7, n = tid & 127;
            int h = half * 2 + seg;
            float s0 = (sec == 0) ? scale : 1.f;
            uint32_t wv[16];
#pragma unroll
            for (int l = 0; l < 16; l++)
                wv[l] = packh2(stg[(seg * 32 + 2 * l) * STG + n] * s0,
                               stg[(seg * 32 + 2 * l + 1) * STG + n] * s0);
            __half* dstp = (sec == 0) ? g_q : g_k;
            uint4* dk = (uint4*)(dstp + ((size_t)(b * H_ + h) * N_ + nBase + n) * D_);
#pragma unroll
            for (int i = 0; i < 4; i++) dk[i] = ((uint4*)wv)[i];
        } else {
            // V: single fp16 [bh][d][j]
            int mrow = tid & 63, n0 = (tid >> 6) * 32;
            int o = half * 64 + mrow;
            int h = o >> 5, d = o & 31;
            uint32_t hw[16];
#pragma unroll
            for (int l = 0; l < 16; l++)
                hw[l] = packh2(stg[mrow * STG + n0 + 2 * l],
                               stg[mrow * STG + n0 + 2 * l + 1]);
            uint4* dv = (uint4*)(g_v + ((size_t)(b * H_ + h) * D_ + d) * N_ + nBase + n0);
#pragma unroll
            for (int i = 0; i < 4; i++) dv[i] = ((uint4*)hw)[i];
        }
    }
}

// ---------------------------------------------------------------------------
// Kernel C: out projection. grid (32 n, 2 m, 4 b), 256 thr.
// ---------------------------------------------------------------------------
__global__ void __launch_bounds__(256) out_mma_kernel(const float* __restrict__ w,
                                                      const float* __restrict__ bias,
                                                      float* __restrict__ out)
{
    __shared__ __align__(16) uint32_t sm[SMEMW];
    float* stg = (float*)sm;

    const int tid  = threadIdx.x;
    const int wid  = tid >> 5;
    const int lane = tid & 31;
    const int nBase = blockIdx.x * 128;
    const int oBase = blockIdx.y * 128;
    const int b     = blockIdx.z;
    const uint32_t sb = smem_u32(sm);

    const float* Aptr = w + (size_t)oBase * HID;
    const float* Bptr = g_att + (size_t)b * HID * N_;

    float C[16][4];
#pragma unroll
    for (int i = 0; i < 16; i++)
#pragma unroll
        for (int j = 0; j < 4; j++) C[i][j] = 0.f;

    CR r;
    ldg_chunk(r, Aptr, Bptr, 0, HID, nBase, tid);
#pragma unroll 1
    for (int k0 = 0; k0 < HID; k0 += 32) {
        __syncthreads();
        sts_chunk(sm, r, tid);
        __syncthreads();
        if (k0 + 32 < HID) ldg_chunk(r, Aptr, Bptr, k0 + 32, HID, nBase, tid);
        mma_chunk(C, sb, wid, lane);
    }

#pragma unroll 1
    for (int half = 0; half < 2; half++) {
        __syncthreads();
        stage_half(stg, C, wid, lane, half);
        __syncthreads();

        int rr = tid & 63, n0 = (tid >> 6) * 32;
        int o = oBase + half * 64 + rr;
        float bv = bias[o];
        float v[32];
#pragma unroll
        for (int i = 0; i < 32; i++) v[i] = stg[rr * STG + n0 + i] + bv;
        float4* dst = (float4*)(out + ((size_t)(b * CIN + o)) * N_ + nBase + n0);
#pragma unroll
        for (int i = 0; i < 8; i++) dst[i] = ((float4*)v)[i];
    }
}

// ---------------------------------------------------------------------------
// Kernel B: flash attention, fp16 mma, single-term S and PV. 3-stage cp.async.
// grid (32 qtiles, 16 bh), 256 thr = 8 warps x 16 q-rows. Key tile = 64.
// smem/stage: K 64x80B + V 32x144B = 9728 B, 3 stages = 29184 B.
// (R8 version — known 116 us; two syncs per tile.)
// ---------------------------------------------------------------------------
#define KOFF    0
#define VOFF    5120
#define STAGE_B 9728
#define NTILES  (N_ / 64)

__global__ void __launch_bounds__(256, 2) attn_mma_kernel()
{
    __shared__ __align__(16) char smb[3 * STAGE_B];
    const uint32_t sb = smem_u32(smb);

    const int tid  = threadIdx.x;
    const int wid  = tid >> 5;
    const int lane = tid & 31;
    const int lq   = lane >> 2;
    const int lr   = lane & 3;

    const int bh = blockIdx.y;
    const int qt = blockIdx.x;

    const char* KG = (const char*)(g_k + (size_t)bh * N_ * D_);
    const char* VG = (const char*)(g_v + (size_t)bh * D_ * N_);
    const int krow = tid >> 2, kseg = tid & 3;
    const int vrow = tid >> 3, vseg = tid & 7;
    const uint32_t kDst = (uint32_t)(krow * 80 + kseg * 16);
    const uint32_t vDst = (uint32_t)(vrow * 144 + vseg * 16);
    const int kSrc = krow * 64 + kseg * 16;     // + jt*64 bytes
    const int vSrc = vrow * 8192 + vseg * 16;   // + jt*2 bytes

    const int rbase = ((lane >> 4) << 3) + (lane & 7);
    const int coff  = (lane & 8) << 1;

    // ---- Q A-frags: single fp16, loaded directly from gmem ----
    uint32_t qf[2][4];
    {
        const __half* Qg = g_q + ((size_t)bh * N_ + qt * 128 + wid * 16) * D_;
#pragma unroll
        for (int ks = 0; ks < 2; ks++) {
            int c0 = ks * 16 + lr * 2;
            qf[ks][0] = *(const uint32_t*)(Qg + (size_t)lq * D_ + c0);
            qf[ks][1] = *(const uint32_t*)(Qg + (size_t)(lq + 8) * D_ + c0);
            qf[ks][2] = *(const uint32_t*)(Qg + (size_t)lq * D_ + c0 + 8);
            qf[ks][3] = *(const uint32_t*)(Qg + (size_t)(lq + 8) * D_ + c0 + 8);
        }
    }

    float O[4][4];
#pragma unroll
    for (int a = 0; a < 4; a++)
#pragma unroll
        for (int c = 0; c < 4; c++) O[a][c] = 0.f;
    float lrow0 = 0.f, lrow1 = 0.f;

    // prologue: tiles 0,1 -> stages 0,1
#pragma unroll
    for (int p = 0; p < 2; p++) {
        uint32_t s = sb + p * STAGE_B;
        CPA16(s + KOFF + kDst, KG + p * 64 * 64 + kSrc);
        CPA16(s + VOFF + vDst, VG + p * 64 * 2 + vSrc);
        asm volatile("cp.async.commit_group;");
    }

    int stage = 0;
#pragma unroll 1
    for (int t = 0; t < NTILES; t++) {
        if (t + 2 < NTILES) {
            const int jt = (t + 2) * 64;
            uint32_t s = sb + ((stage + 2) % 3) * STAGE_B;
            CPA16(s + KOFF + kDst, KG + jt * 64 + kSrc);
            CPA16(s + VOFF + vDst, VG + jt * 2 + vSrc);
            asm volatile("cp.async.commit_group;");
            asm volatile("cp.async.wait_group 2;");
        } else if (t + 1 < NTILES) {
            asm volatile("cp.async.wait_group 1;");
        } else {
            asm volatile("cp.async.wait_group 0;");
        }
        __syncthreads();

        const uint32_t s = sb + stage * STAGE_B;

        // ---- S = Q K^T + softmax (ex2) ----
        uint32_t Pf[4][4];
#pragma unroll
        for (int nbp = 0; nbp < 4; nbp++) {
            float S0[4] = {0.f, 0.f, 0.f, 0.f};
            float S1[4] = {0.f, 0.f, 0.f, 0.f};
#pragma unroll
            for (int ks = 0; ks < 2; ks++) {
                uint32_t kk[4];
                ldm_x4(kk, s + KOFF + (uint32_t)((nbp * 16 + rbase) * 80 + ks * 32 + coff));
                mma16816h(S0, qf[ks], kk[0], kk[1]);
                mma16816h(S1, qf[ks], kk[2], kk[3]);
            }
            float p0 = ex2f(S0[0]);
            float p1 = ex2f(S0[1]);
            float p2 = ex2f(S0[2]);
            float p3 = ex2f(S0[3]);
            float r0 = ex2f(S1[0]);
            float r1 = ex2f(S1[1]);
            float r2 = ex2f(S1[2]);
            float r3 = ex2f(S1[3]);
            lrow0 += p0 + p1 + r0 + r1;
            lrow1 += p2 + p3 + r2 + r3;
            Pf[nbp][0] = packh2(p0, p1);
            Pf[nbp][1] = packh2(p2, p3);
            Pf[nbp][2] = packh2(r0, r1);
            Pf[nbp][3] = packh2(r2, r3);
        }

        // ---- O += P V ----
#pragma unroll
        for (int ts = 0; ts < 4; ts++) {
#pragma unroll
            for (int dbp = 0; dbp < 2; dbp++) {
                uint32_t vv[4];
                ldm_x4(vv, s + VOFF + (uint32_t)((dbp * 16 + rbase) * 144 + ts * 32 + coff));
                mma16816h(O[2 * dbp],     Pf[ts], vv[0], vv[1]);
                mma16816h(O[2 * dbp + 1], Pf[ts], vv[2], vv[3]);
            }
        }
        __syncthreads();

        stage = (stage + 1) % 3;
    }

    // ---- reduce row sums across the 4 lanes sharing a row ----
    lrow0 += __shfl_xor_sync(0xFFFFFFFFu, lrow0, 1);
    lrow0 += __shfl_xor_sync(0xFFFFFFFFu, lrow0, 2);
    lrow1 += __shfl_xor_sync(0xFFFFFFFFu, lrow1, 1);
    lrow1 += __shfl_xor_sync(0xFFFFFFFFu, lrow1, 2);
    const float inv0 = 1.f / lrow0;
    const float inv1 = 1.f / lrow1;

    // ---- write O to g_att [bh*32+d][i] ----
    const int i0 = qt * 128 + wid * 16 + lq;
    float* base = g_att + (size_t)bh * D_ * N_;
#pragma unroll
    for (int db = 0; db < 4; db++) {
        int d = db * 8 + lr * 2;
        base[(size_t)d * N_ + i0]           = O[db][0] * inv0;
        base[(size_t)(d + 1) * N_ + i0]     = O[db][1] * inv0;
        base[(size_t)d * N_ + i0 + 8]       = O[db][2] * inv1;
        base[(size_t)(d + 1) * N_ + i0 + 8] = O[db][3] * inv1;
    }
}

// ---------------------------------------------------------------------------
extern "C" void kernel_launch(void* const* d_in, const int* in_sizes, int n_in,
                              void* d_out, int out_size)
{
    (void)in_sizes; (void)n_in; (void)out_size;
    const float* x     = (const float*)d_in[0];
    const float* w_qkv = (const float*)d_in[1];
    const float* w_out = (const float*)d_in[2];
    const float* b_out = (const float*)d_in[3];
    float* out = (float*)d_out;

    dim3 gA(N_ / 128, 3, B_);
    qkv_mma_kernel<<<gA, 256>>>(x, w_qkv);

    dim3 gB(N_ / 128, BH);
    attn_mma_kernel<<<gB, 256>>>();

    dim3 gC(N_ / 128, 2, B_);
    out_mma_kernel<<<gC, 256>>>(w_out, b_out, out);
}